// round 14
// baseline (speedup 1.0000x reference)
#include <cuda_runtime.h>
#include <cuda_fp16.h>
#include <math.h>
#include <stdint.h>

#define L_ 2
#define F_ 128
#define O_ 128
#define N_ 1024
#define B_ 8
#define D_ 3

// ---------------- scratch (device globals, POD only) ------------------------
__device__ unsigned short g_adjH [(size_t)D_ * B_ * N_ * N_];       // 48 MB
__device__ unsigned short g_x2   [(size_t)B_ * N_ * F_];
__device__ unsigned short g_sup2 [(size_t)D_ * B_ * 2 * N_ * O_];   // B-split
__device__ unsigned short g_agg2 [(size_t)D_ * B_ * N_ * O_];       // single
__device__ float g_aggp [(size_t)2 * D_ * B_ * N_ * O_];            // split-K partials
__device__ unsigned short g_bigB [(size_t)L_ * 2 * F_ * 896];
__device__ unsigned short g_wih2 [(size_t)L_ * 2 * O_ * 3 * O_];
__device__ float g_cbias[(size_t)L_ * 896];
__device__ float g_gi   [(size_t)D_ * B_ * N_ * 3 * O_];
__device__ float g_ghthw[(size_t)B_ * N_ * 512];
__device__ float g_x    [(size_t)N_ * B_ * O_];

// ---------------- fp16 helpers ----------------------------------------------
__device__ __forceinline__ void hsplit2(float a, float b, uint32_t& hi, uint32_t& lo) {
    __half2 h2 = __floats2half2_rn(a, b);
    hi = *reinterpret_cast<const uint32_t*>(&h2);
    __half2 l2 = __floats2half2_rn(a - __low2float(h2), b - __high2float(h2));
    lo = *reinterpret_cast<const uint32_t*>(&l2);
}
__device__ __forceinline__ uint32_t hpack2(float a, float b) {
    __half2 h2 = __floats2half2_rn(a, b);
    return *reinterpret_cast<const uint32_t*>(&h2);
}
__device__ __forceinline__ void hsplit1(float v, unsigned short& hi, unsigned short& lo) {
    __half h = __float2half_rn(v);
    __half l = __float2half_rn(v - __half2float(h));
    hi = *reinterpret_cast<const unsigned short*>(&h);
    lo = *reinterpret_cast<const unsigned short*>(&l);
}

// cvtA: fp32 (strided) [z][M][K] -> fp16 single out[z][M][K]
__global__ void cvtA_kernel(const float* __restrict__ in,
                            unsigned short* __restrict__ out,
                            long inBatch, long inRow, int M, int K) {
    long idx = (long)blockIdx.x * blockDim.x + threadIdx.x;
    long total = (long)M * (K / 8);
    if (idx >= total) return;
    int m = (int)(idx / (K / 8));
    int kc = (int)(idx % (K / 8)) * 8;
    const float* src = in + (long)blockIdx.z * inBatch + (long)m * inRow + kc;
    float4 v0 = *(const float4*)(src);
    float4 v1 = *(const float4*)(src + 4);
    uint32_t p0 = hpack2(v0.x, v0.y);
    uint32_t p1 = hpack2(v0.z, v0.w);
    uint32_t p2 = hpack2(v1.x, v1.y);
    uint32_t p3 = hpack2(v1.z, v1.w);
    unsigned short* dst = out + (long)blockIdx.z * M * K + (long)m * K + kc;
    *(uint4*)(dst) = make_uint4(p0, p1, p2, p3);
}

// prep_all: builds bigB [L][2F][896], wih2 [L][2O][3O], cbias [L][896]
__global__ void prep_all_kernel(const float* __restrict__ W,
                                const float* __restrict__ Bc,
                                const float* __restrict__ Wh,
                                const float* __restrict__ Bh,
                                const float* __restrict__ Wih,
                                const float* __restrict__ Whh,
                                const float* __restrict__ bhh,
                                unsigned short* __restrict__ bigB,
                                unsigned short* __restrict__ wih2,
                                float* __restrict__ cbias) {
    const int T1 = L_ * F_ * 896;
    const int T2 = L_ * 3 * O_ * O_;
    const int T3 = L_ * 896;
    int idx = blockIdx.x * blockDim.x + threadIdx.x;
    if (idx < T1) {
        int l = idx / (F_ * 896);
        int r = idx % (F_ * 896);
        int k = r / 896;
        int n = r % 896;
        float v;
        if (n < 384)      v = W[(((long)l * D_ + (n >> 7)) * F_ + k) * O_ + (n & 127)];
        else if (n < 768) v = Whh[((long)l * 384 + (n - 384)) * O_ + k];
        else              v = Wh[((long)l * F_ + k) * O_ + (n - 768)];
        unsigned short h, lo;
        hsplit1(v, h, lo);
        unsigned short* dst = bigB + (long)l * 2 * F_ * 896;
        dst[(long)k * 896 + n] = h;
        dst[(long)(F_ + k) * 896 + n] = lo;
    } else if (idx < T1 + T2) {
        int j = idx - T1;
        int l = j / (3 * O_ * O_);
        int r = j % (3 * O_ * O_);
        int n = r / O_;
        int k = r % O_;
        float v = Wih[j];
        unsigned short h, lo;
        hsplit1(v, h, lo);
        unsigned short* dst = wih2 + (long)l * 2 * O_ * 3 * O_;
        dst[(long)k * (3 * O_) + n] = h;
        dst[(long)(O_ + k) * (3 * O_) + n] = lo;
    } else if (idx < T1 + T2 + T3) {
        int j = idx - T1 - T2;
        int l = j / 896;
        int n = j % 896;
        float bv;
        if (n < 384)      bv = Bc[(l * D_ + (n >> 7)) * O_ + (n & 127)];
        else if (n < 768) bv = bhh[l * 384 + (n - 384)];
        else              bv = Bh[l * 128 + (n - 768)];
        cbias[j] = bv;
    }
}

// reduce split-K partials: agg2 = fp16( p[0] + p[1] )
__global__ void reduce_agg_kernel(const float* __restrict__ p,
                                  unsigned short* __restrict__ agg2) {
    const long total = (long)D_ * B_ * N_ * O_;
    long idx = ((long)blockIdx.x * blockDim.x + threadIdx.x) * 4;
    if (idx >= total) return;
    float4 a = *(const float4*)(p + idx);
    float4 b = *(const float4*)(p + total + idx);
    uint32_t q0 = hpack2(a.x + b.x, a.y + b.y);
    uint32_t q1 = hpack2(a.z + b.z, a.w + b.w);
    *(uint2*)(agg2 + idx) = make_uint2(q0, q1);
}

// ---------------- tensor-core GEMM primitives (R10 proven core) --------------
__device__ __forceinline__ void ldsm_x4(uint32_t* r, uint32_t addr) {
    asm volatile("ldmatrix.sync.aligned.m8n8.x4.shared.b16 {%0,%1,%2,%3}, [%4];"
                 : "=r"(r[0]), "=r"(r[1]), "=r"(r[2]), "=r"(r[3]) : "r"(addr));
}
__device__ __forceinline__ void ldsm_x2t(uint32_t* r, uint32_t addr) {
    asm volatile("ldmatrix.sync.aligned.m8n8.x2.trans.shared.b16 {%0,%1}, [%2];"
                 : "=r"(r[0]), "=r"(r[1]) : "r"(addr));
}
__device__ __forceinline__ void mma_f16(float* d, const uint32_t* a, const uint32_t* b) {
    asm volatile("mma.sync.aligned.m16n8k16.row.col.f32.f16.f16.f32 "
                 "{%0,%1,%2,%3}, {%4,%5,%6,%7}, {%8,%9}, {%0,%1,%2,%3};"
                 : "+f"(d[0]), "+f"(d[1]), "+f"(d[2]), "+f"(d[3])
                 : "r"(a[0]), "r"(a[1]), "r"(a[2]), "r"(a[3]), "r"(b[0]), "r"(b[1]));
}
__device__ __forceinline__ void cp16(uint32_t smem, const void* gptr) {
    asm volatile("cp.async.cg.shared.global [%0], [%1], 16;" :: "r"(smem), "l"(gptr));
}
__device__ __forceinline__ void cp_commit() { asm volatile("cp.async.commit_group;"); }
__device__ __forceinline__ void cp_wait2()  { asm volatile("cp.async.wait_group 2;"); }

// C[z][m][n] = sum over nT 32-k tiles of A[m][aOff] * B2[bOff][n] (+ bias[n])
// A: [M][K] single fp16; B2: [2K][N]=[Bh;Bl] fp16. aOff wraps at K.
// Tile 128x128x32, 8 warps (2x4), warp 64x32, cp.async 4-stage pipeline.
// emode: 0 fp32 out; 1 fp16 hi/lo B-layout (lo rows +M); 2 fp16 single;
//        3 combined (sup2 + ghthw); 4 split-K agg: blockIdx.y bit3 selects
//        K-half (B2 += half*N*O rows), fp32 partial -> Cout + half*total.
__global__ __launch_bounds__(256, 2)
void gemm_f16_kernel(const unsigned short* __restrict__ A2,
                     const unsigned short* __restrict__ B2,
                     void* __restrict__ Cout, const float* __restrict__ bias,
                     int M, int K, int Ncols,
                     long sAd, long sAb, long sBd, long sBb,
                     long sCb, long sBiasD, int BB, int emode,
                     void* __restrict__ Cout2, int nT) {
    const int z = blockIdx.z;
    const int d = z / BB;
    const int b = z % BB;
    A2 += (long)d * sAd + (long)b * sAb;
    B2 += (long)d * sBd + (long)b * sBb;

    int row0, col0, half = 0;
    if (emode == 4) {
        half = blockIdx.y >> 3;
        row0 = (blockIdx.y & 7) * 128;
        col0 = 0;
        B2 += (long)half * ((long)N_ * O_);   // select Bh rows or Bl rows
    } else {
        row0 = blockIdx.y * 128;
        col0 = blockIdx.x * 128;
    }

    __shared__ uint4 As4[4][512];
    __shared__ uint4 Bs4[4][512];

    const int tid  = threadIdx.x;
    const int lane = tid & 31;
    const int warp = tid >> 5;
    const int wm = warp >> 2;
    const int wn = warp & 3;

    const int arow0 = tid >> 2, ac = tid & 3;
    const int brow0 = tid >> 4, bc = tid & 15;

    const unsigned short* Ag0 = A2 + (long)(row0 + arow0) * K + ac * 8;
    const unsigned short* Ag1 = A2 + (long)(row0 + arow0 + 64) * K + ac * 8;
    const unsigned short* Bg0 = B2 + (long)brow0 * Ncols + col0 + bc * 8;
    const unsigned short* Bg1 = B2 + (long)(brow0 + 16) * Ncols + col0 + bc * 8;

    const int asIdx0 = arow0 * 4 + (ac ^ ((arow0 >> 1) & 3));
    const int asIdx1 = asIdx0 + 256;
    const int bsIdx0 = brow0 * 16 + (bc ^ (brow0 & 7));
    const int bsIdx1 = bsIdx0 + 256;

    const uint32_t asB = (uint32_t)__cvta_generic_to_shared(&As4[0][0]);
    const uint32_t bsB = (uint32_t)__cvta_generic_to_shared(&Bs4[0][0]);

    const uint32_t stA0 = asB + (uint32_t)asIdx0 * 16u;
    const uint32_t stA1 = asB + (uint32_t)asIdx1 * 16u;
    const uint32_t stB0 = bsB + (uint32_t)bsIdx0 * 16u;
    const uint32_t stB1 = bsB + (uint32_t)bsIdx1 * 16u;

    uint32_t aAddr[2][4], bAddr[2][4];
#pragma unroll
    for (int ks = 0; ks < 2; ks++) {
#pragma unroll
        for (int mi = 0; mi < 4; mi++) {
            int r = wm * 64 + mi * 16 + (lane & 15);
            int c = ks * 2 + (lane >> 4);
            aAddr[ks][mi] = asB + (uint32_t)(r * 4 + (c ^ ((r >> 1) & 3))) * 16u;
        }
#pragma unroll
        for (int ni = 0; ni < 4; ni++) {
            int r = ks * 16 + (lane & 15);
            int c = wn * 4 + ni;
            bAddr[ks][ni] = bsB + (uint32_t)(r * 16 + (c ^ (r & 7))) * 16u;
        }
    }

    float acc[4][4][4];
#pragma unroll
    for (int mi = 0; mi < 4; mi++)
#pragma unroll
        for (int ni = 0; ni < 4; ni++)
#pragma unroll
            for (int q = 0; q < 4; q++) acc[mi][ni][q] = 0.f;

    auto issue = [&](int kt, int stg) {
        const int k2 = kt << 5;
        const int aOff = k2 - (k2 >= K ? K : 0);
        const int bOff = k2;
        const uint32_t so = (uint32_t)stg * 8192u;
        cp16(stA0 + so, Ag0 + aOff);
        cp16(stA1 + so, Ag1 + aOff);
        cp16(stB0 + so, Bg0 + (long)bOff * Ncols);
        cp16(stB1 + so, Bg1 + (long)bOff * Ncols);
    };

    issue(0, 0); cp_commit();
    issue(1, 1); cp_commit();

    for (int kt = 0; kt < nT; kt++) {
        if (kt + 2 < nT) issue(kt + 2, (kt + 2) & 3);
        cp_commit();
        cp_wait2();
        __syncthreads();

        const uint32_t bofs = (uint32_t)(kt & 3) * 8192u;
#pragma unroll
        for (int ks = 0; ks < 2; ks++) {
            uint32_t afr[4][4], bfr[4][2];
#pragma unroll
            for (int mi = 0; mi < 4; mi++) ldsm_x4(afr[mi], aAddr[ks][mi] + bofs);
#pragma unroll
            for (int ni = 0; ni < 4; ni++) ldsm_x2t(bfr[ni], bAddr[ks][ni] + bofs);
#pragma unroll
            for (int mi = 0; mi < 4; mi++)
#pragma unroll
                for (int ni = 0; ni < 4; ni++)
                    mma_f16(acc[mi][ni], afr[mi], bfr[ni]);
        }
    }

    const float* bp = bias ? (bias + (long)d * sBiasD) : (const float*)0;
    float* Cf = (float*)Cout + (long)z * sCb;
    unsigned short* Cb = (unsigned short*)Cout + (long)z * sCb;
    if (emode == 4)
        Cf = (float*)Cout + (long)half * ((long)D_ * B_ * N_ * O_) + (long)z * sCb;

#pragma unroll
    for (int mi = 0; mi < 4; mi++) {
        const int r0 = row0 + wm * 64 + mi * 16 + (lane >> 2);
        const int r1 = r0 + 8;
#pragma unroll
        for (int ni = 0; ni < 4; ni++) {
            const int cc = col0 + wn * 32 + ni * 8 + (lane & 3) * 2;
            float bx = 0.f, by = 0.f;
            if (bp) { bx = bp[cc]; by = bp[cc + 1]; }
            const float v00 = acc[mi][ni][0] + bx;
            const float v01 = acc[mi][ni][1] + by;
            const float v10 = acc[mi][ni][2] + bx;
            const float v11 = acc[mi][ni][3] + by;
            if (emode == 0 || emode == 4) {
                float* p0 = Cf + (long)r0 * Ncols + cc;
                float* p1 = Cf + (long)r1 * Ncols + cc;
                p0[0] = v00; p0[1] = v01;
                p1[0] = v10; p1[1] = v11;
            } else if (emode == 1) {
                uint32_t h0, l0, h1, l1;
                hsplit2(v00, v01, h0, l0);
                hsplit2(v10, v11, h1, l1);
                *(uint32_t*)(Cb + (long)r0 * Ncols + cc)       = h0;
                *(uint32_t*)(Cb + (long)(M + r0) * Ncols + cc) = l0;
                *(uint32_t*)(Cb + (long)r1 * Ncols + cc)       = h1;
                *(uint32_t*)(Cb + (long)(M + r1) * Ncols + cc) = l1;
            } else if (emode == 2) {
                *(uint32_t*)(Cb + (long)r0 * Ncols + cc) = hpack2(v00, v01);
                *(uint32_t*)(Cb + (long)r1 * Ncols + cc) = hpack2(v10, v11);
            } else {  // emode 3: combined support (cols<384) + ghthw (cols>=384)
                if (blockIdx.x < 3) {
                    unsigned short* S = (unsigned short*)Cout
                        + (long)(blockIdx.x * B_ + z) * (2L * N_ * O_);
                    const int lc = cc & 127;
                    uint32_t h0, l0, h1, l1;
                    hsplit2(v00, v01, h0, l0);
                    hsplit2(v10, v11, h1, l1);
                    *(uint32_t*)(S + (long)r0 * O_ + lc)        = h0;
                    *(uint32_t*)(S + (long)(N_ + r0) * O_ + lc) = l0;
                    *(uint32_t*)(S + (long)r1 * O_ + lc)        = h1;
                    *(uint32_t*)(S + (long)(N_ + r1) * O_ + lc) = l1;
                } else {
                    float* G = (float*)Cout2 + (long)z * ((long)N_ * 512);
                    const int lc = cc - 384;
                    G[(long)r0 * 512 + lc]     = v00;
                    G[(long)r0 * 512 + lc + 1] = v01;
                    G[(long)r1 * 512 + lc]     = v10;
                    G[(long)r1 * 512 + lc + 1] = v11;
                }
            }
        }
    }
}

// ---------------- fused GRU + d-sum + relu + highway (+ next-layer cvt) -----
__device__ __forceinline__ float sigm(float x) { return 1.f / (1.f + expf(-x)); }

__global__ void gru_combine_kernel(const float* __restrict__ gi,
                                   const float* __restrict__ ghthw,
                                   const float* __restrict__ xsrc,
                                   float* __restrict__ xdst,
                                   unsigned short* __restrict__ x2out) {
    int idx = blockIdx.x * blockDim.x + threadIdx.x;  // (n,b,o)
    if (idx >= N_ * B_ * O_) return;
    const int o = idx & (O_ - 1);
    const int nb = idx / O_;
    const int b = nb & (B_ - 1);
    const int n = nb / B_;

    const float h = xsrc[idx];
    const long gbase512 = ((long)b * N_ + n) * 512;
    const float ghr = ghthw[gbase512 + o];
    const float ghz = ghthw[gbase512 + O_ + o];
    const float ghn = ghthw[gbase512 + 2 * O_ + o];
    const float traw = ghthw[gbase512 + 3 * O_ + o];

    float acc = 0.f;
#pragma unroll
    for (int d = 0; d < D_; d++) {
        const long gbase = (((long)d * B_ + b) * N_ + n) * (3 * O_);
        const float gir = gi[gbase + o];
        const float giz = gi[gbase + O_ + o];
        const float gin = gi[gbase + 2 * O_ + o];
        const float r = sigm(gir + ghr);
        const float zz = sigm(giz + ghz);
        const float nn = tanhf(gin + r * ghn);
        acc += (1.f - zz) * nn + zz * h;
    }
    const float outv = fmaxf(acc, 0.f);
    const float t = fmaxf(traw, 0.f);
    const float val = outv * t + h * (1.f - t);
    xdst[idx] = val;
    if (x2out) {
        __half hv = __float2half_rn(val);
        x2out[((long)b * N_ + n) * F_ + o] = *reinterpret_cast<const unsigned short*>(&hv);
    }
}

// ---------------- launch ----------------------------------------------------
extern "C" void kernel_launch(void* const* d_in, const int* in_sizes, int n_in,
                              void* d_out, int out_size) {
    const float* inputs = (const float*)d_in[0];
    const float* adj    = (const float*)d_in[1];
    const float* W      = (const float*)d_in[2];
    const float* Bc     = (const float*)d_in[3];
    const float* Wh     = (const float*)d_in[4];
    const float* Bh     = (const float*)d_in[5];
    const float* Wih    = (const float*)d_in[6];
    const float* Whh    = (const float*)d_in[7];
    const float* bih    = (const float*)d_in[8];
    const float* bhh    = (const float*)d_in[9];
    float* out = (float*)d_out;

    unsigned short *adjH, *x2, *sup2, *agg2, *bigB, *wih2;
    float *aggp, *cbias, *gi, *ghthw, *xbuf;
    cudaGetSymbolAddress((void**)&adjH,  g_adjH);
    cudaGetSymbolAddress((void**)&x2,    g_x2);
    cudaGetSymbolAddress((void**)&sup2,  g_sup2);
    cudaGetSymbolAddress((void**)&agg2,  g_agg2);
    cudaGetSymbolAddress((void**)&aggp,  g_aggp);
    cudaGetSymbolAddress((void**)&bigB,  g_bigB);
    cudaGetSymbolAddress((void**)&wih2,  g_wih2);
    cudaGetSymbolAddress((void**)&cbias, g_cbias);
    cudaGetSymbolAddress((void**)&gi,    g_gi);
    cudaGetSymbolAddress((void**)&ghthw, g_ghthw);
    cudaGetSymbolAddress((void**)&xbuf,  g_x);

    // ---- one-time conversions (3 launches) ----
    cvtA_kernel<<<dim3((N_ * N_ / 8 + 255) / 256, 1, D_ * B_), 256>>>(
        adj, adjH, (long)N_ * N_, (long)N_, N_, N_);
    cvtA_kernel<<<dim3((N_ * F_ / 8 + 255) / 256, 1, B_), 256>>>(
        inputs, x2, (long)F_, (long)B_ * F_, N_, F_);
    {
        const int total = L_ * F_ * 896 + L_ * 3 * O_ * O_ + L_ * 896;
        prep_all_kernel<<<(total + 255) / 256, 256>>>(
            W, Bc, Wh, Bh, Wih, Whh, bhh, bigB, wih2, cbias);
    }

    for (int l = 0; l < L_; l++) {
        const float* xs = (l == 0) ? inputs : xbuf;
        float* xd = (l == L_ - 1) ? out : xbuf;

        // combined: cols 0..383 -> sup2[d][b] (fp16 hi/lo), cols 384..895 -> ghthw
        gemm_f16_kernel<<<dim3(7, N_ / 128, B_), 256>>>(
            x2, bigB + (long)l * 2 * F_ * 896, sup2, cbias + (long)l * 896,
            N_, F_, 896,
            0, (long)N_ * F_, 0, 0,
            0, 0, B_, 3, ghthw, 8);

        // split-K agg: grid.y in [0,16): bit3 = K-half; partials -> aggp
        gemm_f16_kernel<<<dim3(1, 16, D_ * B_), 256>>>(
            adjH, sup2, aggp, (const float*)0,
            N_, N_, O_,
            (long)B_ * N_ * N_, (long)N_ * N_,
            (long)B_ * 2 * N_ * O_, (long)2 * N_ * O_,
            (long)N_ * O_, 0, B_, 4, (void*)0, 32);

        // agg2 = fp16( aggp[0] + aggp[1] )
        reduce_agg_kernel<<<(D_ * B_ * N_ * O_ / 4 + 255) / 256, 256>>>(aggp, agg2);

        // gi[d,b][n][3O] = agg2[d,b] @ Wih[l]^T + bih[l]
        gemm_f16_kernel<<<dim3(3, N_ / 128, D_ * B_), 256>>>(
            agg2, wih2 + (long)l * 2 * O_ * 3 * O_, gi, bih + (long)l * 3 * O_,
            N_, O_, 3 * O_,
            (long)B_ * N_ * O_, (long)N_ * O_, 0, 0,
            (long)N_ * 3 * O_, 0, B_, 0, (void*)0, 8);

        gru_combine_kernel<<<(N_ * B_ * O_) / 256, 256>>>(
            gi, ghthw, xs, xd, (l < L_ - 1) ? x2 : (unsigned short*)0);
    }
}

// round 16
// speedup vs baseline: 1.0318x; 1.0318x over previous
#include <cuda_runtime.h>
#include <cuda_fp16.h>
#include <math.h>
#include <stdint.h>

#define L_ 2
#define F_ 128
#define O_ 128
#define N_ 1024
#define B_ 8
#define D_ 3

// ---------------- scratch (device globals, POD only) ------------------------
__device__ unsigned short g_adjH [(size_t)D_ * B_ * N_ * N_];       // 48 MB
__device__ unsigned short g_x2   [(size_t)B_ * N_ * F_];
__device__ unsigned short g_sup2 [(size_t)D_ * B_ * 2 * N_ * O_];   // B-split
__device__ unsigned short g_agg2 [(size_t)D_ * B_ * N_ * O_];       // single
__device__ unsigned short g_bigB [(size_t)L_ * 2 * F_ * 896];   // [2F][ W d0|d1|d2 | Whh^T | Wh ]
__device__ unsigned short g_wih2 [(size_t)L_ * 2 * O_ * 3 * O_];
__device__ float g_cbias[(size_t)L_ * 896];
__device__ float g_gi   [(size_t)D_ * B_ * N_ * 3 * O_];
__device__ float g_ghthw[(size_t)B_ * N_ * 512];
__device__ float g_x    [(size_t)N_ * B_ * O_];

// ---------------- fp16 helpers ----------------------------------------------
__device__ __forceinline__ void hsplit2(float a, float b, uint32_t& hi, uint32_t& lo) {
    __half2 h2 = __floats2half2_rn(a, b);
    hi = *reinterpret_cast<const uint32_t*>(&h2);
    __half2 l2 = __floats2half2_rn(a - __low2float(h2), b - __high2float(h2));
    lo = *reinterpret_cast<const uint32_t*>(&l2);
}
__device__ __forceinline__ uint32_t hpack2(float a, float b) {
    __half2 h2 = __floats2half2_rn(a, b);
    return *reinterpret_cast<const uint32_t*>(&h2);
}
__device__ __forceinline__ void hsplit1(float v, unsigned short& hi, unsigned short& lo) {
    __half h = __float2half_rn(v);
    __half l = __float2half_rn(v - __half2float(h));
    hi = *reinterpret_cast<const unsigned short*>(&h);
    lo = *reinterpret_cast<const unsigned short*>(&l);
}

// ---------------- single mega-prep kernel ------------------------------------
// job 0: adjH = fp16(adj), flat contiguous D*B*N*N (8 elems/thread)
// job 1: x2[b][n][F] = fp16(inputs[n][b][F]) (8 elems/thread)
// job 2: bigB [L][2F][896] = hi/lo of [W d0|d1|d2 | Whh^T | Wh]
// job 3: wih2 [L][2O][3O]
// job 4: cbias [L][896]
__global__ void prep_mega_kernel(const float* __restrict__ adj,
                                 const float* __restrict__ inputs,
                                 const float* __restrict__ W,
                                 const float* __restrict__ Bc,
                                 const float* __restrict__ Wh,
                                 const float* __restrict__ Bh,
                                 const float* __restrict__ Wih,
                                 const float* __restrict__ Whh,
                                 const float* __restrict__ bhh,
                                 unsigned short* __restrict__ adjH,
                                 unsigned short* __restrict__ x2,
                                 unsigned short* __restrict__ bigB,
                                 unsigned short* __restrict__ wih2,
                                 float* __restrict__ cbias) {
    const long T0 = (long)D_ * B_ * N_ * N_ / 8;      // 3,145,728
    const long T1 = (long)B_ * N_ * (F_ / 8);         // 131,072
    const long T2 = (long)L_ * F_ * 896;              // 229,376
    const long T3 = (long)L_ * 3 * O_ * O_;           // 98,304
    const long T4 = (long)L_ * 896;
    long idx = (long)blockIdx.x * blockDim.x + threadIdx.x;

    if (idx < T0) {
        const long e = idx * 8;
        float4 v0 = *(const float4*)(adj + e);
        float4 v1 = *(const float4*)(adj + e + 4);
        *(uint4*)(adjH + e) = make_uint4(hpack2(v0.x, v0.y), hpack2(v0.z, v0.w),
                                         hpack2(v1.x, v1.y), hpack2(v1.z, v1.w));
        return;
    }
    idx -= T0;
    if (idx < T1) {
        const int b = (int)(idx / (N_ * 16));
        const int r = (int)(idx % (N_ * 16));
        const int n = r >> 4;
        const int f = (r & 15) * 8;
        const float* src = inputs + ((long)n * B_ + b) * F_ + f;
        float4 v0 = *(const float4*)(src);
        float4 v1 = *(const float4*)(src + 4);
        unsigned short* dst = x2 + ((long)b * N_ + n) * F_ + f;
        *(uint4*)(dst) = make_uint4(hpack2(v0.x, v0.y), hpack2(v0.z, v0.w),
                                    hpack2(v1.x, v1.y), hpack2(v1.z, v1.w));
        return;
    }
    idx -= T1;
    if (idx < T2) {
        int l = (int)(idx / (F_ * 896));
        int r = (int)(idx % (F_ * 896));
        int k = r / 896;
        int n = r % 896;
        float v;
        if (n < 384)      v = W[(((long)l * D_ + (n >> 7)) * F_ + k) * O_ + (n & 127)];
        else if (n < 768) v = Whh[((long)l * 384 + (n - 384)) * O_ + k];
        else              v = Wh[((long)l * F_ + k) * O_ + (n - 768)];
        unsigned short h, lo;
        hsplit1(v, h, lo);
        unsigned short* dst = bigB + (long)l * 2 * F_ * 896;
        dst[(long)k * 896 + n] = h;
        dst[(long)(F_ + k) * 896 + n] = lo;
        return;
    }
    idx -= T2;
    if (idx < T3) {
        int l = (int)(idx / (3 * O_ * O_));
        int r = (int)(idx % (3 * O_ * O_));
        int n = r / O_;
        int k = r % O_;
        float v = Wih[(long)l * 3 * O_ * O_ + r];
        unsigned short h, lo;
        hsplit1(v, h, lo);
        unsigned short* dst = wih2 + (long)l * 2 * O_ * 3 * O_;
        dst[(long)k * (3 * O_) + n] = h;
        dst[(long)(O_ + k) * (3 * O_) + n] = lo;
        return;
    }
    idx -= T3;
    if (idx < T4) {
        int l = (int)(idx / 896);
        int n = (int)(idx % 896);
        float bv;
        if (n < 384)      bv = Bc[(l * D_ + (n >> 7)) * O_ + (n & 127)];
        else if (n < 768) bv = bhh[l * 384 + (n - 384)];
        else              bv = Bh[l * 128 + (n - 768)];
        cbias[(long)l * 896 + n] = bv;
    }
}

// ---------------- tensor-core GEMM primitives (R12 proven core) --------------
__device__ __forceinline__ void ldsm_x4(uint32_t* r, uint32_t addr) {
    asm volatile("ldmatrix.sync.aligned.m8n8.x4.shared.b16 {%0,%1,%2,%3}, [%4];"
                 : "=r"(r[0]), "=r"(r[1]), "=r"(r[2]), "=r"(r[3]) : "r"(addr));
}
__device__ __forceinline__ void ldsm_x2t(uint32_t* r, uint32_t addr) {
    asm volatile("ldmatrix.sync.aligned.m8n8.x2.trans.shared.b16 {%0,%1}, [%2];"
                 : "=r"(r[0]), "=r"(r[1]) : "r"(addr));
}
__device__ __forceinline__ void mma_f16(float* d, const uint32_t* a, const uint32_t* b) {
    asm volatile("mma.sync.aligned.m16n8k16.row.col.f32.f16.f16.f32 "
                 "{%0,%1,%2,%3}, {%4,%5,%6,%7}, {%8,%9}, {%0,%1,%2,%3};"
                 : "+f"(d[0]), "+f"(d[1]), "+f"(d[2]), "+f"(d[3])
                 : "r"(a[0]), "r"(a[1]), "r"(a[2]), "r"(a[3]), "r"(b[0]), "r"(b[1]));
}
__device__ __forceinline__ void cp16(uint32_t smem, const void* gptr) {
    asm volatile("cp.async.cg.shared.global [%0], [%1], 16;" :: "r"(smem), "l"(gptr));
}
__device__ __forceinline__ void cp_commit() { asm volatile("cp.async.commit_group;"); }
__device__ __forceinline__ void cp_wait2()  { asm volatile("cp.async.wait_group 2;"); }

// C[z][m][n] = sum_{k2<2K} A[m][aOff(k2)] * B2[k2][n] (+ bias[n])
// A: [M][K] single fp16; B2: [2K][N]=[Bh;Bl] fp16.
// terms: A*Bh (k2<K), A*Bl (k2>=K): aOff = k2 - (k2>=K ? K : 0), bOff = k2.
// Tile 128x128x32, 8 warps (2x4), warp 64x32, cp.async 4-stage pipeline.
// emode: 0 fp32 out; 1 fp16 hi/lo B-layout (lo rows +M); 2 fp16 single
//        [m][Ncols]; 3 combined: blockIdx.x<3 -> sup2 (per-d B-layout),
//        else -> ghthw fp32 [z][1024][512] (Cout2).
__global__ __launch_bounds__(256, 2)
void gemm_f16_kernel(const unsigned short* __restrict__ A2,
                     const unsigned short* __restrict__ B2,
                     void* __restrict__ Cout, const float* __restrict__ bias,
                     int M, int K, int Ncols,
                     long sAd, long sAb, long sBd, long sBb,
                     long sCb, long sBiasD, int BB, int emode,
                     void* __restrict__ Cout2) {
    const int z = blockIdx.z;
    const int d = z / BB;
    const int b = z % BB;
    A2 += (long)d * sAd + (long)b * sAb;
    B2 += (long)d * sBd + (long)b * sBb;

    const int row0 = blockIdx.y * 128;
    const int col0 = blockIdx.x * 128;

    __shared__ uint4 As4[4][512];
    __shared__ uint4 Bs4[4][512];

    const int tid  = threadIdx.x;
    const int lane = tid & 31;
    const int warp = tid >> 5;
    const int wm = warp >> 2;
    const int wn = warp & 3;

    const int arow0 = tid >> 2, ac = tid & 3;
    const int brow0 = tid >> 4, bc = tid & 15;

    const unsigned short* Ag0 = A2 + (long)(row0 + arow0) * K + ac * 8;
    const unsigned short* Ag1 = A2 + (long)(row0 + arow0 + 64) * K + ac * 8;
    const unsigned short* Bg0 = B2 + (long)brow0 * Ncols + col0 + bc * 8;
    const unsigned short* Bg1 = B2 + (long)(brow0 + 16) * Ncols + col0 + bc * 8;

    const int asIdx0 = arow0 * 4 + (ac ^ ((arow0 >> 1) & 3));
    const int asIdx1 = asIdx0 + 256;
    const int bsIdx0 = brow0 * 16 + (bc ^ (brow0 & 7));
    const int bsIdx1 = bsIdx0 + 256;

    const uint32_t asB = (uint32_t)__cvta_generic_to_shared(&As4[0][0]);
    const uint32_t bsB = (uint32_t)__cvta_generic_to_shared(&Bs4[0][0]);

    const uint32_t stA0 = asB + (uint32_t)asIdx0 * 16u;
    const uint32_t stA1 = asB + (uint32_t)asIdx1 * 16u;
    const uint32_t stB0 = bsB + (uint32_t)bsIdx0 * 16u;
    const uint32_t stB1 = bsB + (uint32_t)bsIdx1 * 16u;

    uint32_t aAddr[2][4], bAddr[2][4];
#pragma unroll
    for (int ks = 0; ks < 2; ks++) {
#pragma unroll
        for (int mi = 0; mi < 4; mi++) {
            int r = wm * 64 + mi * 16 + (lane & 15);
            int c = ks * 2 + (lane >> 4);
            aAddr[ks][mi] = asB + (uint32_t)(r * 4 + (c ^ ((r >> 1) & 3))) * 16u;
        }
#pragma unroll
        for (int ni = 0; ni < 4; ni++) {
            int r = ks * 16 + (lane & 15);
            int c = wn * 4 + ni;
            bAddr[ks][ni] = bsB + (uint32_t)(r * 16 + (c ^ (r & 7))) * 16u;
        }
    }

    float acc[4][4][4];
#pragma unroll
    for (int mi = 0; mi < 4; mi++)
#pragma unroll
        for (int ni = 0; ni < 4; ni++)
#pragma unroll
            for (int q = 0; q < 4; q++) acc[mi][ni][q] = 0.f;

    const int nT = (2 * K) >> 5;

    auto issue = [&](int kt, int stg) {
        const int k2 = kt << 5;
        const int aOff = k2 - (k2 >= K ? K : 0);
        const int bOff = k2;
        const uint32_t so = (uint32_t)stg * 8192u;
        cp16(stA0 + so, Ag0 + aOff);
        cp16(stA1 + so, Ag1 + aOff);
        cp16(stB0 + so, Bg0 + (long)bOff * Ncols);
        cp16(stB1 + so, Bg1 + (long)bOff * Ncols);
    };

    issue(0, 0); cp_commit();
    issue(1, 1); cp_commit();

    for (int kt = 0; kt < nT; kt++) {
        if (kt + 2 < nT) issue(kt + 2, (kt + 2) & 3);
        cp_commit();
        cp_wait2();
        __syncthreads();

        const uint32_t bofs = (uint32_t)(kt & 3) * 8192u;
#pragma unroll
        for (int ks = 0; ks < 2; ks++) {
            uint32_t afr[4][4], bfr[4][2];
#pragma unroll
            for (int mi = 0; mi < 4; mi++) ldsm_x4(afr[mi], aAddr[ks][mi] + bofs);
#pragma unroll
            for (int ni = 0; ni < 4; ni++) ldsm_x2t(bfr[ni], bAddr[ks][ni] + bofs);
#pragma unroll
            for (int mi = 0; mi < 4; mi++)
#pragma unroll
                for (int ni = 0; ni < 4; ni++)
                    mma_f16(acc[mi][ni], afr[mi], bfr[ni]);
        }
    }

    const float* bp = bias ? (bias + (long)d * sBiasD) : (const float*)0;
    float* Cf = (float*)Cout + (long)z * sCb;
    unsigned short* Cb = (unsigned short*)Cout + (long)z * sCb;

#pragma unroll
    for (int mi = 0; mi < 4; mi++) {
        const int r0 = row0 + wm * 64 + mi * 16 + (lane >> 2);
        const int r1 = r0 + 8;
#pragma unroll
        for (int ni = 0; ni < 4; ni++) {
            const int cc = col0 + wn * 32 + ni * 8 + (lane & 3) * 2;
            float bx = 0.f, by = 0.f;
            if (bp) { bx = bp[cc]; by = bp[cc + 1]; }
            const float v00 = acc[mi][ni][0] + bx;
            const float v01 = acc[mi][ni][1] + by;
            const float v10 = acc[mi][ni][2] + bx;
            const float v11 = acc[mi][ni][3] + by;
            if (emode == 0) {
                float* p0 = Cf + (long)r0 * Ncols + cc;
                float* p1 = Cf + (long)r1 * Ncols + cc;
                p0[0] = v00; p0[1] = v01;
                p1[0] = v10; p1[1] = v11;
            } else if (emode == 1) {
                uint32_t h0, l0, h1, l1;
                hsplit2(v00, v01, h0, l0);
                hsplit2(v10, v11, h1, l1);
                *(uint32_t*)(Cb + (long)r0 * Ncols + cc)       = h0;
                *(uint32_t*)(Cb + (long)(M + r0) * Ncols + cc) = l0;
                *(uint32_t*)(Cb + (long)r1 * Ncols + cc)       = h1;
                *(uint32_t*)(Cb + (long)(M + r1) * Ncols + cc) = l1;
            } else if (emode == 2) {
                *(uint32_t*)(Cb + (long)r0 * Ncols + cc) = hpack2(v00, v01);
                *(uint32_t*)(Cb + (long)r1 * Ncols + cc) = hpack2(v10, v11);
            } else {  // emode 3: combined support (cols<384) + ghthw (cols>=384)
                if (blockIdx.x < 3) {
                    unsigned short* S = (unsigned short*)Cout
                        + (long)(blockIdx.x * B_ + z) * (2L * N_ * O_);
                    const int lc = cc & 127;
                    uint32_t h0, l0, h1, l1;
                    hsplit2(v00, v01, h0, l0);
                    hsplit2(v10, v11, h1, l1);
                    *(uint32_t*)(S + (long)r0 * O_ + lc)        = h0;
                    *(uint32_t*)(S + (long)(N_ + r0) * O_ + lc) = l0;
                    *(uint32_t*)(S + (long)r1 * O_ + lc)        = h1;
                    *(uint32_t*)(S + (long)(N_ + r1) * O_ + lc) = l1;
                } else {
                    float* G = (float*)Cout2 + (long)z * ((long)N_ * 512);
                    const int lc = cc - 384;
                    G[(long)r0 * 512 + lc]     = v00;
                    G[(long)r0 * 512 + lc + 1] = v01;
                    G[(long)r1 * 512 + lc]     = v10;
                    G[(long)r1 * 512 + lc + 1] = v11;
                }
            }
        }
    }
}

// ---------------- fused GRU + d-sum + relu + highway (float4, + cvt) --------
__device__ __forceinline__ float sigm(float x) { return 1.f / (1.f + expf(-x)); }

__global__ void gru_combine_kernel(const float* __restrict__ gi,
                                   const float* __restrict__ ghthw,
                                   const float* __restrict__ xsrc,
                                   float* __restrict__ xdst,
                                   unsigned short* __restrict__ x2out) {
    int vid = blockIdx.x * blockDim.x + threadIdx.x;   // (n,b,o4)
    if (vid >= N_ * B_ * O_ / 4) return;
    const int o = (vid & 31) * 4;
    const int nb = vid >> 5;
    const int b = nb & (B_ - 1);
    const int n = nb / B_;

    const float4 h4 = *(const float4*)(xsrc + (long)nb * O_ + o);
    const long g512 = ((long)b * N_ + n) * 512;
    const float4 ghr4 = *(const float4*)(ghthw + g512 + o);
    const float4 ghz4 = *(const float4*)(ghthw + g512 + O_ + o);
    const float4 ghn4 = *(const float4*)(ghthw + g512 + 2 * O_ + o);
    const float4 t4   = *(const float4*)(ghthw + g512 + 3 * O_ + o);

    const float h[4]   = {h4.x, h4.y, h4.z, h4.w};
    const float ghr[4] = {ghr4.x, ghr4.y, ghr4.z, ghr4.w};
    const float ghz[4] = {ghz4.x, ghz4.y, ghz4.z, ghz4.w};
    const float ghn[4] = {ghn4.x, ghn4.y, ghn4.z, ghn4.w};
    float acc[4] = {0.f, 0.f, 0.f, 0.f};

#pragma unroll
    for (int d = 0; d < D_; d++) {
        const long gb = (((long)d * B_ + b) * N_ + n) * (3 * O_);
        const float4 gir4 = *(const float4*)(gi + gb + o);
        const float4 giz4 = *(const float4*)(gi + gb + O_ + o);
        const float4 gin4 = *(const float4*)(gi + gb + 2 * O_ + o);
        const float gir[4] = {gir4.x, gir4.y, gir4.z, gir4.w};
        const float giz[4] = {giz4.x, giz4.y, giz4.z, giz4.w};
        const float gin[4] = {gin4.x, gin4.y, gin4.z, gin4.w};
#pragma unroll
        for (int i = 0; i < 4; i++) {
            const float r = sigm(gir[i] + ghr[i]);
            const float zz = sigm(giz[i] + ghz[i]);
            const float nn = tanhf(gin[i] + r * ghn[i]);
            acc[i] += (1.f - zz) * nn + zz * h[i];
        }
    }
    const float tr[4] = {t4.x, t4.y, t4.z, t4.w};
    float val[4];
#pragma unroll
    for (int i = 0; i < 4; i++) {
        const float outv = fmaxf(acc[i], 0.f);
        const float t = fmaxf(tr[i], 0.f);
        val[i] = outv * t + h[i] * (1.f - t);
    }
    *(float4*)(xdst + (long)nb * O_ + o) = make_float4(val[0], val[1], val[2], val[3]);
    if (x2out) {
        uint32_t q0 = hpack2(val[0], val[1]);
        uint32_t q1 = hpack2(val[2], val[3]);
        *(uint2*)(x2out + ((long)b * N_ + n) * F_ + o) = make_uint2(q0, q1);
    }
}

// ---------------- launch ----------------------------------------------------
extern "C" void kernel_launch(void* const* d_in, const int* in_sizes, int n_in,
                              void* d_out, int out_size) {
    const float* inputs = (const float*)d_in[0];
    const float* adj    = (const float*)d_in[1];
    const float* W      = (const float*)d_in[2];
    const float* Bc     = (const float*)d_in[3];
    const float* Wh     = (const float*)d_in[4];
    const float* Bh     = (const float*)d_in[5];
    const float* Wih    = (const float*)d_in[6];
    const float* Whh    = (const float*)d_in[7];
    const float* bih    = (const float*)d_in[8];
    const float* bhh    = (const float*)d_in[9];
    float* out = (float*)d_out;

    unsigned short *adjH, *x2, *sup2, *agg2, *bigB, *wih2;
    float *cbias, *gi, *ghthw, *xbuf;
    cudaGetSymbolAddress((void**)&adjH,  g_adjH);
    cudaGetSymbolAddress((void**)&x2,    g_x2);
    cudaGetSymbolAddress((void**)&sup2,  g_sup2);
    cudaGetSymbolAddress((void**)&agg2,  g_agg2);
    cudaGetSymbolAddress((void**)&bigB,  g_bigB);
    cudaGetSymbolAddress((void**)&wih2,  g_wih2);
    cudaGetSymbolAddress((void**)&cbias, g_cbias);
    cudaGetSymbolAddress((void**)&gi,    g_gi);
    cudaGetSymbolAddress((void**)&ghthw, g_ghthw);
    cudaGetSymbolAddress((void**)&xbuf,  g_x);

    // ---- one-time conversions (1 launch) ----
    {
        const long total = (long)D_ * B_ * N_ * N_ / 8 + (long)B_ * N_ * (F_ / 8)
                         + (long)L_ * F_ * 896 + (long)L_ * 3 * O_ * O_ + (long)L_ * 896;
        const int blocks = (int)((total + 255) / 256);
        prep_mega_kernel<<<blocks, 256>>>(adj, inputs, W, Bc, Wh, Bh, Wih, Whh, bhh,
                                          adjH, x2, bigB, wih2, cbias);
    }

    for (int l = 0; l < L_; l++) {
        const float* xs = (l == 0) ? inputs : xbuf;
        float* xd = (l == L_ - 1) ? out : xbuf;

        // combined: cols 0..383 -> sup2[d][b] (fp16 hi/lo), cols 384..895 -> ghthw
        gemm_f16_kernel<<<dim3(7, N_ / 128, B_), 256>>>(
            x2, bigB + (long)l * 2 * F_ * 896, sup2, cbias + (long)l * 896,
            N_, F_, 896,
            0, (long)N_ * F_, 0, 0,
            0, 0, B_, 3, ghthw);

        // agg2[d,b] (fp16 single [N][O]) = adjH[d,b] @ sup2[d,b]
        gemm_f16_kernel<<<dim3(1, N_ / 128, D_ * B_), 256>>>(
            adjH, sup2, agg2, (const float*)0,
            N_, N_, O_,
            (long)B_ * N_ * N_, (long)N_ * N_,
            (long)B_ * 2 * N_ * O_, (long)2 * N_ * O_,
            (long)N_ * O_, 0, B_, 2, (void*)0);

        // gi[d,b][n][3O] = agg2[d,b] @ Wih[l]^T + bih[l]
        gemm_f16_kernel<<<dim3(3, N_ / 128, D_ * B_), 256>>>(
            agg2, wih2 + (long)l * 2 * O_ * 3 * O_, gi, bih + (long)l * 3 * O_,
            N_, O_, 3 * O_,
            (long)B_ * N_ * O_, (long)N_ * O_, 0, 0,
            (long)N_ * 3 * O_, 0, B_, 0, (void*)0);

        gru_combine_kernel<<<(N_ * B_ * O_ / 4 + 255) / 256, 256>>>(
            gi, ghthw, xs, xd, (l < L_ - 1) ? x2 : (unsigned short*)0);
    }
}